// round 6
// baseline (speedup 1.0000x reference)
#include <cuda_runtime.h>
#include <math.h>

// Problem constants (fixed by setup_inputs): N=16, T=2048, D=2
#define TT 2048
#define NBMAX 16
#define LOG2PI_F 1.8378770664093453f
#define LN2F     0.6931471805599453f

// Scratch (device globals; no allocation allowed)
__device__ float4 g_pack[NBMAX * TT];   // (A_j, xs_j, ys_j, 0)
__device__ float  g_logP[NBMAX * TT];   // log( sum_{j<i} exp(t_j/sp) )

__device__ __forceinline__ float ex2f(float x) {
    float r;
    asm("ex2.approx.f32 %0, %1;" : "=f"(r) : "f"(x));
    return r;
}

// ---------------------------------------------------------------------------
// Kernel A: per batch, build packed per-j data and prefix logP.
//   c2_j = t_j / (sp * ln2)            (log2 domain)
//   A_j  = c2_j - h2l*(xj^2+yj^2)
//   xs_j = 2*h2l*xj ; ys_j = 2*h2l*yj
//   E_j  = 2^{c2_j};  P_i = sum_{j<i} E_j ; g_logP[i] = ln(P_i)
// ---------------------------------------------------------------------------
__global__ void prep_kernel(const float* __restrict__ tim,
                            const float* __restrict__ loc,
                            const float* __restrict__ cd_p,
                            const float* __restrict__ sls_p) {
    const int n   = blockIdx.x;
    const int tid = threadIdx.x;           // 256 threads
    const float cd  = *cd_p;
    const float sls = *sls_p;
    const float sp  = log1pf(__expf(cd));          // softplus(coeff_decay)
    const float rc2 = 1.0f / (sp * LN2F);
    const float h2l = 0.5f * __expf(-2.0f * sls) / LN2F;

    __shared__ float sE[TT];
    __shared__ float wtot[8];
    __shared__ float wbase[8];

    for (int j = tid; j < TT; j += 256) {
        float tj = tim[n * TT + j];
        float xj = loc[(n * TT + j) * 2 + 0];
        float yj = loc[(n * TT + j) * 2 + 1];
        float c2 = tj * rc2;
        float A  = fmaf(-h2l, fmaf(xj, xj, yj * yj), c2);
        float xs = 2.0f * h2l * xj;
        float ys = 2.0f * h2l * yj;
        g_pack[n * TT + j] = make_float4(A, xs, ys, 0.0f);
        sE[j] = ex2f(c2);
    }
    __syncthreads();

    // Block-wide exclusive scan of sE (2048 elems, 8 per thread)
    const int C = TT / 256;                // 8
    float part = 0.0f;
#pragma unroll
    for (int k = 0; k < C; k++) part += sE[tid * C + k];

    float inc = part;
    const int lane = tid & 31;
#pragma unroll
    for (int o = 1; o < 32; o <<= 1) {
        float v = __shfl_up_sync(0xffffffffu, inc, o);
        if (lane >= o) inc += v;
    }
    if (lane == 31) wtot[tid >> 5] = inc;
    __syncthreads();
    if (tid < 8) {
        float v = wtot[tid], s = v;
#pragma unroll
        for (int o = 1; o < 8; o <<= 1) {
            float u = __shfl_up_sync(0x000000ffu, s, o);
            if (tid >= o) s += u;
        }
        wbase[tid] = s - v;                // exclusive warp base
    }
    __syncthreads();

    float run = wbase[tid >> 5] + (inc - part);   // exclusive base of this chunk
#pragma unroll
    for (int k = 0; k < C; k++) {
        int j = tid * C + k;
        g_logP[n * TT + j] = (j == 0) ? 0.0f : __logf(run);
        run += sE[j];
    }
}

// ---------------------------------------------------------------------------
// Per-warp partial for tile r: lane owns row i = 32r + lane; this warp covers
// dense j-chunk [4r*wid, 4r*(wid+1)); warp `tailwid` also does the 31-step
// predicated triangular tail. 8-deep independent load front for MLP.
// ---------------------------------------------------------------------------
__device__ __forceinline__ float tile_partial(const float4* __restrict__ pk,
                                              int r, int wid, int lane,
                                              float xi, float yi, int tailwid) {
    const int C    = r << 2;               // 4r (multiple of 4)
    int       j    = wid * C;
    const int jend = j + C;

    float s0 = 0.0f, s1 = 0.0f, s2 = 0.0f, s3 = 0.0f;
    for (; j + 8 <= jend; j += 8) {
        float4 p0 = pk[j + 0]; float4 p1 = pk[j + 1];
        float4 p2 = pk[j + 2]; float4 p3 = pk[j + 3];
        float4 p4 = pk[j + 4]; float4 p5 = pk[j + 5];
        float4 p6 = pk[j + 6]; float4 p7 = pk[j + 7];
        s0 += ex2f(fmaf(xi, p0.y, fmaf(yi, p0.z, p0.x)));
        s1 += ex2f(fmaf(xi, p1.y, fmaf(yi, p1.z, p1.x)));
        s2 += ex2f(fmaf(xi, p2.y, fmaf(yi, p2.z, p2.x)));
        s3 += ex2f(fmaf(xi, p3.y, fmaf(yi, p3.z, p3.x)));
        s0 += ex2f(fmaf(xi, p4.y, fmaf(yi, p4.z, p4.x)));
        s1 += ex2f(fmaf(xi, p5.y, fmaf(yi, p5.z, p5.x)));
        s2 += ex2f(fmaf(xi, p6.y, fmaf(yi, p6.z, p6.x)));
        s3 += ex2f(fmaf(xi, p7.y, fmaf(yi, p7.z, p7.x)));
    }
    if (j < jend) {                        // exactly 4 remain (C % 8 == 4)
        float4 p0 = pk[j + 0]; float4 p1 = pk[j + 1];
        float4 p2 = pk[j + 2]; float4 p3 = pk[j + 3];
        s0 += ex2f(fmaf(xi, p0.y, fmaf(yi, p0.z, p0.x)));
        s1 += ex2f(fmaf(xi, p1.y, fmaf(yi, p1.z, p1.x)));
        s2 += ex2f(fmaf(xi, p2.y, fmaf(yi, p2.z, p2.x)));
        s3 += ex2f(fmaf(xi, p3.y, fmaf(yi, p3.z, p3.x)));
    }

    // Triangular tail: j = 32r + jt, active for lanes with jt < lane
    if (wid == tailwid) {
        const int jb = r << 5;
#pragma unroll 1
        for (int jt = 0; jt < 31; jt++) {
            float4 q = pk[jb + jt];
            float e = ex2f(fmaf(xi, q.y, fmaf(yi, q.z, q.x)));
            s1 += (jt < lane) ? e : 0.0f;
        }
    }
    return (s0 + s1) + (s2 + s3);
}

// ---------------------------------------------------------------------------
// Kernel B: one block = 8 warps = tile pair (rA=p, rB=63-p) of one batch.
// Uniform work: every warp does 4*rA + 4*rB = 252 dense j's.
// __launch_bounds__(256, 1): lift the register cap so the 8-deep load front
// survives (R5 regression: ptxas capped at 32 regs and serialized all loads).
// ---------------------------------------------------------------------------
__global__ void __launch_bounds__(256, 1)
main_kernel(const float* __restrict__ loc,
            const float* __restrict__ mu0_p,
            const float* __restrict__ ls0_p,
            const float* __restrict__ sls_p,
            float* __restrict__ out) {
    const int b    = blockIdx.x;
    const int n    = b >> 5;               // 32 tile-pairs per batch
    const int p    = b & 31;
    const int rA   = p;
    const int rB   = 63 - p;
    const int wid  = threadIdx.x >> 5;
    const int lane = threadIdx.x & 31;

    __shared__ float sacc[2][8][32];

    const float sls = *sls_p;
    const float h2l = 0.5f * __expf(-2.0f * sls) / LN2F;

    const int iA = (rA << 5) + lane;
    const int iB = (rB << 5) + lane;
    const float xiA = loc[(n * TT + iA) * 2 + 0];
    const float yiA = loc[(n * TT + iA) * 2 + 1];
    const float xiB = loc[(n * TT + iB) * 2 + 0];
    const float yiB = loc[(n * TT + iB) * 2 + 1];

    const float4* __restrict__ pk = &g_pack[n * TT];

    sacc[0][wid][lane] = tile_partial(pk, rA, wid, lane, xiA, yiA, 7);
    sacc[1][wid][lane] = tile_partial(pk, rB, wid, lane, xiB, yiB, 6);
    __syncthreads();

    if (wid < 2) {
        const int r = (wid == 0) ? rA : rB;
        const int i = (r << 5) + lane;
        const float xi = (wid == 0) ? xiA : xiB;
        const float yi = (wid == 0) ? yiA : yiB;

        float S = 0.0f;
#pragma unroll
        for (int w = 0; w < 8; w++) S += sacc[wid][w][lane];

        float res;
        if (i == 0) {
            const float mu0 = *mu0_p;
            const float ls0 = *ls0_p;
            const float iv  = __expf(-2.0f * ls0);
            const float dx = xi - mu0, dy = yi - mu0;
            res = -0.5f * iv * fmaf(dx, dx, dy * dy) - 2.0f * ls0 - LOG2PI_F;
        } else {
            const float B2 = -h2l * fmaf(xi, xi, yi * yi);
            const float K  = 2.0f * sls + LOG2PI_F;
            res = __logf(S) + LN2F * B2 - K - g_logP[n * TT + i];
        }
        out[n * TT + i] = res;
    }
}

// ---------------------------------------------------------------------------
extern "C" void kernel_launch(void* const* d_in, const int* in_sizes, int n_in,
                              void* d_out, int out_size) {
    const float* tim  = (const float*)d_in[0];  // (N, T, 1)
    const float* loc  = (const float*)d_in[1];  // (N, T, 2)
    const float* mu0  = (const float*)d_in[2];
    const float* ls0  = (const float*)d_in[3];
    const float* cd   = (const float*)d_in[4];
    const float* sls  = (const float*)d_in[5];
    float* out = (float*)d_out;

    const int N = in_sizes[0] / TT;             // 16

    prep_kernel<<<N, 256>>>(tim, loc, cd, sls);
    main_kernel<<<N * 32, 256>>>(loc, mu0, ls0, sls, out);
}

// round 7
// speedup vs baseline: 1.3364x; 1.3364x over previous
#include <cuda_runtime.h>
#include <math.h>

// Problem constants (fixed by setup_inputs): N=16, T=2048, D=2
#define TT 2048
#define NBMAX 16
#define LOG2PI_F 1.8378770664093453f
#define LN2F     0.6931471805599453f

// Scratch (device globals; no allocation allowed)
__device__ float4 g_pack[NBMAX * TT];   // (A_j, xs_j, ys_j, 0)
__device__ float  g_logP[NBMAX * TT];   // log( sum_{j<i} exp(t_j/sp) )

__device__ __forceinline__ float ex2f(float x) {
    float r;
    asm("ex2.approx.f32 %0, %1;" : "=f"(r) : "f"(x));
    return r;
}

// ---------------------------------------------------------------------------
// Kernel A: per batch, build packed per-j data and prefix logP.
//   c2_j = t_j / (sp * ln2)            (log2 domain)
//   A_j  = c2_j - h2l*(xj^2+yj^2)
//   xs_j = 2*h2l*xj ; ys_j = 2*h2l*yj
//   E_j  = 2^{c2_j};  P_i = sum_{j<i} E_j ; g_logP[i] = ln(P_i)
// ---------------------------------------------------------------------------
__global__ void prep_kernel(const float* __restrict__ tim,
                            const float* __restrict__ loc,
                            const float* __restrict__ cd_p,
                            const float* __restrict__ sls_p) {
    const int n   = blockIdx.x;
    const int tid = threadIdx.x;           // 256 threads
    const float cd  = *cd_p;
    const float sls = *sls_p;
    const float sp  = log1pf(__expf(cd));          // softplus(coeff_decay)
    const float rc2 = 1.0f / (sp * LN2F);
    const float h2l = 0.5f * __expf(-2.0f * sls) / LN2F;

    __shared__ float sE[TT];
    __shared__ float wtot[8];
    __shared__ float wbase[8];

    for (int j = tid; j < TT; j += 256) {
        float tj = tim[n * TT + j];
        float xj = loc[(n * TT + j) * 2 + 0];
        float yj = loc[(n * TT + j) * 2 + 1];
        float c2 = tj * rc2;
        float A  = fmaf(-h2l, fmaf(xj, xj, yj * yj), c2);
        float xs = 2.0f * h2l * xj;
        float ys = 2.0f * h2l * yj;
        g_pack[n * TT + j] = make_float4(A, xs, ys, 0.0f);
        sE[j] = ex2f(c2);
    }
    __syncthreads();

    // Block-wide exclusive scan of sE (2048 elems, 8 per thread)
    const int C = TT / 256;                // 8
    float part = 0.0f;
#pragma unroll
    for (int k = 0; k < C; k++) part += sE[tid * C + k];

    float inc = part;
    const int lane = tid & 31;
#pragma unroll
    for (int o = 1; o < 32; o <<= 1) {
        float v = __shfl_up_sync(0xffffffffu, inc, o);
        if (lane >= o) inc += v;
    }
    if (lane == 31) wtot[tid >> 5] = inc;
    __syncthreads();
    if (tid < 8) {
        float v = wtot[tid], s = v;
#pragma unroll
        for (int o = 1; o < 8; o <<= 1) {
            float u = __shfl_up_sync(0x000000ffu, s, o);
            if (tid >= o) s += u;
        }
        wbase[tid] = s - v;                // exclusive warp base
    }
    __syncthreads();

    float run = wbase[tid >> 5] + (inc - part);   // exclusive base of this chunk
#pragma unroll
    for (int k = 0; k < C; k++) {
        int j = tid * C + k;
        g_logP[n * TT + j] = (j == 0) ? 0.0f : __logf(run);
        run += sE[j];
    }
}

// ---------------------------------------------------------------------------
// Kernel B: block = one batch-slice of 8 tiles; warp w owns tile:
//   w<4 : k + 8w        (light)
//   w>=4: 63 - k - 8(w-4) (heavy, complement of warp w-4 on the same SMSP)
// Every SMSP thus carries exactly 63*32 = 2016 warp-j -> uniform MUFU load.
// The block double-buffers 256-float4 chunks of g_pack through smem; all
// warps read the same chunk via LDS broadcast. Lane owns row i=32*tile+lane.
// Grid = 16*8 = 128 blocks -> one wave, one block per SM.
// ---------------------------------------------------------------------------
__global__ void __launch_bounds__(256, 1)
main_kernel(const float* __restrict__ loc,
            const float* __restrict__ mu0_p,
            const float* __restrict__ ls0_p,
            const float* __restrict__ sls_p,
            float* __restrict__ out) {
    const int b    = blockIdx.x;
    const int n    = b >> 3;               // batch
    const int k    = b & 7;                // slice
    const int tid  = threadIdx.x;
    const int wid  = tid >> 5;
    const int lane = tid & 31;

    const int tile = (wid < 4) ? (k + (wid << 3))
                               : (63 - k - ((wid - 4) << 3));
    const int rmax    = 63 - k;            // heaviest tile in this block (w=4)
    const int nchunks = ((rmax << 5) + 31 + 255) >> 8;   // chunks incl. tails

    __shared__ float4 sb[2][256];

    const float sls = *sls_p;
    const float h2l = 0.5f * __expf(-2.0f * sls) / LN2F;

    const int i = (tile << 5) + lane;
    const float xi = loc[(n * TT + i) * 2 + 0];
    const float yi = loc[(n * TT + i) * 2 + 1];

    const float4* __restrict__ pk = &g_pack[n * TT];

    // stage chunk 0
    sb[0][tid] = pk[tid];
    __syncthreads();

    const int lim = tile << 5;             // dense j-range [0, lim)
    float s0 = 0.0f, s1 = 0.0f, s2 = 0.0f, s3 = 0.0f;

    for (int c = 0; c < nchunks; c++) {
        float4 v;
        const bool more = (c + 1 < nchunks);
        if (more) v = pk[((c + 1) << 8) + tid];   // prefetch next chunk

        const float4* __restrict__ buf = sb[c & 1];
        const int lo = c << 8;
        int count = lim - lo;
        count = count < 0 ? 0 : (count > 256 ? 256 : count);

        for (int jl = 0; jl < count; jl += 8) {   // count % 32 == 0
            float4 p0 = buf[jl + 0]; float4 p1 = buf[jl + 1];
            float4 p2 = buf[jl + 2]; float4 p3 = buf[jl + 3];
            float4 p4 = buf[jl + 4]; float4 p5 = buf[jl + 5];
            float4 p6 = buf[jl + 6]; float4 p7 = buf[jl + 7];
            s0 += ex2f(fmaf(xi, p0.y, fmaf(yi, p0.z, p0.x)));
            s1 += ex2f(fmaf(xi, p1.y, fmaf(yi, p1.z, p1.x)));
            s2 += ex2f(fmaf(xi, p2.y, fmaf(yi, p2.z, p2.x)));
            s3 += ex2f(fmaf(xi, p3.y, fmaf(yi, p3.z, p3.x)));
            s0 += ex2f(fmaf(xi, p4.y, fmaf(yi, p4.z, p4.x)));
            s1 += ex2f(fmaf(xi, p5.y, fmaf(yi, p5.z, p5.x)));
            s2 += ex2f(fmaf(xi, p6.y, fmaf(yi, p6.z, p6.x)));
            s3 += ex2f(fmaf(xi, p7.y, fmaf(yi, p7.z, p7.x)));
        }

        // Triangular tail lives in chunk (tile>>3): j = 32*tile + jt, jt<lane
        if ((tile >> 3) == c) {
            const int base = (tile & 7) << 5;
#pragma unroll
            for (int jt = 0; jt < 31; jt++) {
                float4 q = buf[base + jt];
                float e = ex2f(fmaf(xi, q.y, fmaf(yi, q.z, q.x)));
                s1 += (jt < lane) ? e : 0.0f;
            }
        }

        __syncthreads();                   // chunk c fully consumed by all
        if (more) sb[(c + 1) & 1][tid] = v;
        __syncthreads();                   // next chunk visible
    }

    // Epilogue: warp-private, no reduction needed
    float res;
    if (i == 0) {
        const float mu0 = *mu0_p;
        const float ls0 = *ls0_p;
        const float iv  = __expf(-2.0f * ls0);
        const float dx = xi - mu0, dy = yi - mu0;
        res = -0.5f * iv * fmaf(dx, dx, dy * dy) - 2.0f * ls0 - LOG2PI_F;
    } else {
        const float S  = (s0 + s1) + (s2 + s3);
        const float B2 = -h2l * fmaf(xi, xi, yi * yi);
        const float K  = 2.0f * sls + LOG2PI_F;
        res = __logf(S) + LN2F * B2 - K - g_logP[n * TT + i];
    }
    out[n * TT + i] = res;
}

// ---------------------------------------------------------------------------
extern "C" void kernel_launch(void* const* d_in, const int* in_sizes, int n_in,
                              void* d_out, int out_size) {
    const float* tim  = (const float*)d_in[0];  // (N, T, 1)
    const float* loc  = (const float*)d_in[1];  // (N, T, 2)
    const float* mu0  = (const float*)d_in[2];
    const float* ls0  = (const float*)d_in[3];
    const float* cd   = (const float*)d_in[4];
    const float* sls  = (const float*)d_in[5];
    float* out = (float*)d_out;

    const int N = in_sizes[0] / TT;             // 16

    prep_kernel<<<N, 256>>>(tim, loc, cd, sls);
    main_kernel<<<N * 8, 256>>>(loc, mu0, ls0, sls, out);
}